// round 9
// baseline (speedup 1.0000x reference)
#include <cuda_runtime.h>
#include <cuda_bf16.h>
#include <cstdint>

#define B_   8
#define C_   64
#define H_   128
#define W_   416
#define OH_  (4 * H_)
#define OW_  (4 * W_)
#define HW_  (H_ * W_)

// Scratch h: conv3x3+relu output, CHANNEL-LAST bf16: [b][y][x][ci] (~54.5 MB).
__device__ __nv_bfloat16 g_h[(size_t)B_ * H_ * W_ * C_];

// ---------------------------------------------------------------------------
// helpers (legacy mma.sync / ldmatrix — compile for plain compute_103)
// ---------------------------------------------------------------------------
__device__ __forceinline__ uint32_t smem_u32(const void* p) {
    uint32_t a;
    asm("{ .reg .u64 t; cvta.to.shared.u64 t, %1; cvt.u32.u64 %0, t; }"
        : "=r"(a) : "l"(p));
    return a;
}

__device__ __forceinline__ void mma_bf16(float* d, const uint32_t* a,
                                         uint32_t b0, uint32_t b1) {
    asm volatile(
        "mma.sync.aligned.m16n8k16.row.col.f32.bf16.bf16.f32 "
        "{%0,%1,%2,%3}, {%4,%5,%6,%7}, {%8,%9}, {%0,%1,%2,%3};"
        : "+f"(d[0]), "+f"(d[1]), "+f"(d[2]), "+f"(d[3])
        : "r"(a[0]), "r"(a[1]), "r"(a[2]), "r"(a[3]), "r"(b0), "r"(b1));
}

__device__ __forceinline__ void ldmx4(uint32_t* r, uint32_t addr) {
    asm volatile(
        "ldmatrix.sync.aligned.m8n8.x4.shared.b16 {%0,%1,%2,%3}, [%4];"
        : "=r"(r[0]), "=r"(r[1]), "=r"(r[2]), "=r"(r[3]) : "r"(addr));
}

// ---------------------------------------------------------------------------
// Kernel A: conv3x3 (pad=1, no bias) + ReLU as bf16 implicit GEMM.
// CTA = 4 rows x 128 px x 64 co, 256 threads (8 warps).
// Warp = 64 px x ALL 64 co: per k-chunk 8 ldmatrix.x4 -> 32 HMMAs (LDSM/HMMA
// ratio halved vs R8) and 32-deep independent-MMA ILP per warp.
// All 9 taps of weights + 6 feat rows staged ONCE -> zero mainloop syncs.
// ---------------------------------------------------------------------------
#define SPADB  144                      // bytes per ci-row (72 bf16 slots)
#define OFF_W  112320                   // feat: 6*130*144
#define WTAP   9216                     // per-tap weights: 64*144
#define SMEM_A_BYTES (112320 + 9 * 9216)   // 195264

__global__ __launch_bounds__(256, 1) void conv3x3_tc_kernel(
    const float* __restrict__ feat, const float* __restrict__ w1)
{
    extern __shared__ char sm[];
    const uint32_t sbase = smem_u32(sm);

    const int x0  = (blockIdx.x < 3) ? blockIdx.x * 128 : (W_ - 128);
    const int y0  = blockIdx.y * 4;
    const int b   = blockIdx.z;
    const int tid = threadIdx.x;
    const int wid = tid >> 5;
    const int lane = tid & 31;
    const int gid = lane >> 2;
    const int tig = lane & 3;

    const int rowsel = wid >> 1;         // output row 0..3
    const int xwbase = (wid & 1) * 64;   // x half

    // ---- Stage feat rows y0-1 .. y0+4 as bf16 pairs, [r][xi][ci] ----
    for (int j = tid; j < 6 * 32 * 130; j += 256) {
        int r   = j / (32 * 130);
        int rem = j - r * (32 * 130);
        int ci2 = rem / 130;
        int xi  = rem - ci2 * 130;
        int yy  = y0 + r - 1;
        int gx  = x0 + xi - 1;
        float f0 = 0.f, f1 = 0.f;
        if ((unsigned)yy < (unsigned)H_ && (unsigned)gx < (unsigned)W_) {
            size_t o = ((size_t)(b * C_ + 2 * ci2) * H_ + yy) * W_ + gx;
            f0 = feat[o];
            f1 = feat[o + (size_t)HW_];
        }
        __nv_bfloat162 v2 = __floats2bfloat162_rn(f0, f1);
        *reinterpret_cast<uint32_t*>(sm + (r * 130 + xi) * SPADB + ci2 * 4) =
            *reinterpret_cast<uint32_t*>(&v2);
    }
    // ---- Stage ALL 9 taps of w1 as bf16 [tap][co][ci] ----
    for (int j = tid; j < 9 * 64 * 32; j += 256) {
        int tap = j >> 11;
        int co  = (j >> 5) & 63;
        int ci2 = j & 31;
        const float* wp = w1 + co * 576 + ci2 * 18 + tap;
        __nv_bfloat162 v2 = __floats2bfloat162_rn(wp[0], wp[9]);
        *reinterpret_cast<uint32_t*>(sm + OFF_W + tap * WTAP + co * SPADB + ci2 * 4) =
            *reinterpret_cast<uint32_t*>(&v2);
    }
    __syncthreads();

    // per-lane ldmatrix offsets
    const uint32_t a_loff = (uint32_t)(((lane & 7) + ((lane >> 3) & 1) * 8) * SPADB
                                       + ((lane >> 4) & 1) * 16);
    const uint32_t b_loff = (uint32_t)((lane & 7) * SPADB + ((lane >> 3) & 1) * 16
                                       + ((lane >> 4) & 1) * (8 * SPADB));

    float acc[4][8][4];
    #pragma unroll
    for (int mf = 0; mf < 4; mf++)
        #pragma unroll
        for (int nf = 0; nf < 8; nf++)
            #pragma unroll
            for (int r = 0; r < 4; r++) acc[mf][nf][r] = 0.f;

    #pragma unroll
    for (int t = 0; t < 9; t++) {
        const int ky = t / 3, kx = t - ky * 3;
        const uint32_t frow = sbase
            + (uint32_t)(((rowsel + ky) * 130 + xwbase + kx) * SPADB) + a_loff;
        const uint32_t wrow = sbase + OFF_W + (uint32_t)(t * WTAP) + b_loff;

        #pragma unroll
        for (int kc = 0; kc < 4; kc++) {
            uint32_t a[4][4];
            #pragma unroll
            for (int mf = 0; mf < 4; mf++)
                ldmx4(a[mf], frow + (uint32_t)(mf * 16 * SPADB + kc * 32));
            uint32_t bf[16];
            #pragma unroll
            for (int i = 0; i < 4; i++)
                ldmx4(bf + 4 * i, wrow + (uint32_t)(i * 16 * SPADB + kc * 32));
            #pragma unroll
            for (int nf = 0; nf < 8; nf++)
                #pragma unroll
                for (int mf = 0; mf < 4; mf++)
                    mma_bf16(acc[mf][nf], a[mf], bf[nf * 2], bf[nf * 2 + 1]);
        }
    }

    // ---- Epilogue: ReLU + store h channel-last bf16 as bf16x2 words ----
    const int yy = y0 + rowsel;
    #pragma unroll
    for (int nf = 0; nf < 8; nf++) {
        const int co = nf * 8 + tig * 2;
        #pragma unroll
        for (int mf = 0; mf < 4; mf++) {
            const int xg = x0 + xwbase + mf * 16 + gid;
            size_t base = (((size_t)b * H_ + yy) * W_ + xg) * C_ + co;
            if (xg < W_) {
                __nv_bfloat162 v = __floats2bfloat162_rn(
                    fmaxf(acc[mf][nf][0], 0.f), fmaxf(acc[mf][nf][1], 0.f));
                *reinterpret_cast<uint32_t*>(&g_h[base]) =
                    *reinterpret_cast<uint32_t*>(&v);
            }
            if (xg + 8 < W_) {
                __nv_bfloat162 v = __floats2bfloat162_rn(
                    fmaxf(acc[mf][nf][2], 0.f), fmaxf(acc[mf][nf][3], 0.f));
                *reinterpret_cast<uint32_t*>(&g_h[base + 8 * C_]) =
                    *reinterpret_cast<uint32_t*>(&v);
            }
        }
    }
}

// ---------------------------------------------------------------------------
// Kernel B: 1x1 conv (64->144) via bf16 mma + softmax(9 taps) + depth blend
// + pixel shuffle. CTA = 64 px of one row, 256 threads (8 warps).
// Logits buffer ALIASES the h/w2 staging region (dead after phase-1 fragment
// reads; extra barrier before scatter) -> smem 68KB -> 38KB -> 5 CTAs/SM.
// ---------------------------------------------------------------------------
#define SHB_OFF   0            // h tile  [64 px][72 bf16]  9216 B   (aliased)
#define SWB_OFF   9216         // w2      [144 co][72 bf16] 20736 B  (aliased)
#define SLOG_OFF  0            // logits  [64][146] f32     37376 B  (aliases above)
#define SDEP_OFF  37376        // depth   [3][66] f32         792 B
#define SMEM_B_BYTES 38168

__global__ __launch_bounds__(256) void mask_upsample_kernel(
    const float* __restrict__ depth, const float* __restrict__ w2,
    float* __restrict__ out)
{
    extern __shared__ char smB[];
    char*  shb  = smB + SHB_OFF;
    char*  swb  = smB + SWB_OFF;
    float* slog = reinterpret_cast<float*>(smB + SLOG_OFF);
    float (*sdep)[66] = reinterpret_cast<float(*)[66]>(smB + SDEP_OFF);

    const int x0  = (blockIdx.x < 6) ? blockIdx.x * 64 : (W_ - 64);
    const int y   = blockIdx.y;
    const int b   = blockIdx.z;
    const int tid = threadIdx.x;
    const int wid = tid >> 5;
    const int lane = tid & 31;
    const int gid = lane >> 2;
    const int tig = lane & 3;
    const int warpM = wid & 3;
    const int warpN = wid >> 2;

    for (int j = tid; j < 64 * 8; j += 256) {
        int px = j >> 3, seg = j & 7;
        int gx = x0 + px;
        uint4 v = make_uint4(0u, 0u, 0u, 0u);
        if (gx < W_)
            v = *reinterpret_cast<const uint4*>(
                g_h + ((((size_t)b * H_ + y) * W_ + gx) * C_ + seg * 8));
        *reinterpret_cast<uint4*>(shb + px * SPADB + seg * 16) = v;
    }
    for (int j = tid; j < 144 * 32; j += 256) {
        int co = j >> 5, ci2 = j & 31;
        const float* wp = w2 + co * 64 + ci2 * 2;
        __nv_bfloat162 v2 = __floats2bfloat162_rn(wp[0], wp[1]);
        *reinterpret_cast<uint32_t*>(swb + co * SPADB + ci2 * 4) =
            *reinterpret_cast<uint32_t*>(&v2);
    }
    for (int i = tid; i < 3 * 66; i += 256) {
        int ry = i / 66, rx = i - ry * 66;
        int gy = y + ry - 1, gx = x0 + rx - 1;
        sdep[ry][rx] = (gy >= 0 && gy < H_ && gx >= 0 && gx < W_)
                       ? depth[((size_t)b * H_ + gy) * W_ + gx] : 0.f;
    }
    __syncthreads();

    // ---- Phase 1: GEMM M=64 N=144 K=64 -> logits in registers ----
    float acc[9][4];
    #pragma unroll
    for (int nf = 0; nf < 9; nf++)
        #pragma unroll
        for (int r = 0; r < 4; r++) acc[nf][r] = 0.f;

    #pragma unroll
    for (int kc = 0; kc < 4; kc++) {
        uint32_t a[4];
        const char* ap = shb + (warpM * 16 + gid) * SPADB + kc * 32 + tig * 4;
        a[0] = *reinterpret_cast<const uint32_t*>(ap);
        a[1] = *reinterpret_cast<const uint32_t*>(ap + 8 * SPADB);
        a[2] = *reinterpret_cast<const uint32_t*>(ap + 16);
        a[3] = *reinterpret_cast<const uint32_t*>(ap + 8 * SPADB + 16);
        #pragma unroll
        for (int nf = 0; nf < 9; nf++) {
            const int co = warpN * 72 + nf * 8 + gid;
            const char* bp = swb + co * SPADB + kc * 32 + tig * 4;
            uint32_t b0 = *reinterpret_cast<const uint32_t*>(bp);
            uint32_t b1 = *reinterpret_cast<const uint32_t*>(bp + 16);
            mma_bf16(acc[nf], a, b0, b1);
        }
    }

    // staging region is dead now; barrier, then reuse it for logits
    __syncthreads();
    {
        const int px = warpM * 16 + gid;
        #pragma unroll
        for (int nf = 0; nf < 9; nf++) {
            const int co = warpN * 72 + nf * 8 + tig * 2;
            *reinterpret_cast<float2*>(&slog[px * 146 + co]) =
                make_float2(acc[nf][0], acc[nf][1]);
            *reinterpret_cast<float2*>(&slog[(px + 8) * 146 + co]) =
                make_float2(acc[nf][2], acc[nf][3]);
        }
    }
    __syncthreads();

    // ---- Phase 2: softmax over taps + depth blend + pixel shuffle ----
    const int px   = tid & 63;
    const int cgrp = tid >> 6;
    float d[9];
    #pragma unroll
    for (int t = 0; t < 9; t++) d[t] = sdep[t / 3][px + (t % 3)];

    float vals[4];
    #pragma unroll
    for (int j = 0; j < 4; j++) {
        const int cell = cgrp * 4 + j;
        float lg[9];
        #pragma unroll
        for (int t = 0; t < 9; t++) lg[t] = slog[px * 146 + t * 16 + cell];
        float mx = lg[0];
        #pragma unroll
        for (int t = 1; t < 9; t++) mx = fmaxf(mx, lg[t]);
        float s = 0.f, v = 0.f;
        #pragma unroll
        for (int t = 0; t < 9; t++) {
            float e = __expf(lg[t] - mx);
            s += e;
            v = fmaf(e, d[t], v);
        }
        vals[j] = v / s;
    }

    const int gx = x0 + px;
    if (gx < W_)
        *reinterpret_cast<float4*>(
            &out[((size_t)b * OH_ + (y * 4 + cgrp)) * OW_ + gx * 4]) =
            make_float4(vals[0], vals[1], vals[2], vals[3]);
}

extern "C" void kernel_launch(void* const* d_in, const int* in_sizes, int n_in,
                              void* d_out, int out_size)
{
    const float* depth = (const float*)d_in[0];
    const float* feat  = (const float*)d_in[1];
    const float* w1    = (const float*)d_in[2];
    const float* w2    = (const float*)d_in[3];
    float* out = (float*)d_out;

    cudaFuncSetAttribute(conv3x3_tc_kernel,
                         cudaFuncAttributeMaxDynamicSharedMemorySize, SMEM_A_BYTES);
    cudaFuncSetAttribute(mask_upsample_kernel,
                         cudaFuncAttributeMaxDynamicSharedMemorySize, SMEM_B_BYTES);

    dim3 gA(4, H_ / 4, B_);                   // 4 x-tiles x 32 y-tiles x 8
    conv3x3_tc_kernel<<<gA, 256, SMEM_A_BYTES>>>(feat, w1);

    dim3 gB(7, H_, B_);                       // 7 x-tiles of 64 px (last clamped)
    mask_upsample_kernel<<<gB, 256, SMEM_B_BYTES>>>(depth, w2, out);
}

// round 10
// speedup vs baseline: 1.1366x; 1.1366x over previous
#include <cuda_runtime.h>
#include <cuda_bf16.h>
#include <cstdint>

#define B_   8
#define C_   64
#define H_   128
#define W_   416
#define OH_  (4 * H_)
#define OW_  (4 * W_)
#define HW_  (H_ * W_)

// Scratch h: conv3x3+relu output, CHANNEL-LAST bf16: [b][y][x][ci] (~54.5 MB).
__device__ __nv_bfloat16 g_h[(size_t)B_ * H_ * W_ * C_];

// ---------------------------------------------------------------------------
// helpers (legacy mma.sync / ldmatrix — compile for plain compute_103)
// ---------------------------------------------------------------------------
__device__ __forceinline__ uint32_t smem_u32(const void* p) {
    uint32_t a;
    asm("{ .reg .u64 t; cvta.to.shared.u64 t, %1; cvt.u32.u64 %0, t; }"
        : "=r"(a) : "l"(p));
    return a;
}

__device__ __forceinline__ void mma_bf16(float* d, const uint32_t* a,
                                         uint32_t b0, uint32_t b1) {
    asm volatile(
        "mma.sync.aligned.m16n8k16.row.col.f32.bf16.bf16.f32 "
        "{%0,%1,%2,%3}, {%4,%5,%6,%7}, {%8,%9}, {%0,%1,%2,%3};"
        : "+f"(d[0]), "+f"(d[1]), "+f"(d[2]), "+f"(d[3])
        : "r"(a[0]), "r"(a[1]), "r"(a[2]), "r"(a[3]), "r"(b0), "r"(b1));
}

__device__ __forceinline__ void ldmx4(uint32_t* r, uint32_t addr) {
    asm volatile(
        "ldmatrix.sync.aligned.m8n8.x4.shared.b16 {%0,%1,%2,%3}, [%4];"
        : "=r"(r[0]), "=r"(r[1]), "=r"(r[2]), "=r"(r[3]) : "r"(addr));
}

// ---------------------------------------------------------------------------
// Kernel A: conv3x3 (pad=1, no bias) + ReLU as bf16 implicit GEMM.
// CTA = 4 rows x 128 px x 64 co, 512 threads (16 warps: 8 M x 2 N).
// Mainloop: 36 fully-unrolled iterations (9 taps x 4 k-chunks), fragments
// double-buffered in registers: prefetch iter i+1's 6 ldmatrix.x4 BEFORE
// issuing iter i's 16 HMMAs -> LDSM latency overlapped with tensor work.
// All taps + 6 feat rows staged once; zero mainloop syncs.
// ---------------------------------------------------------------------------
#define SPADB  144                      // bytes per ci-row (72 bf16 slots)
#define OFF_W  112320                   // feat: 6*130*144
#define WTAP   9216                     // per-tap weights: 64*144
#define SMEM_A_BYTES (112320 + 9 * 9216)   // 195264

__global__ __launch_bounds__(512, 1) void conv3x3_tc_kernel(
    const float* __restrict__ feat, const float* __restrict__ w1)
{
    extern __shared__ char sm[];
    const uint32_t sbase = smem_u32(sm);

    const int x0  = (blockIdx.x < 3) ? blockIdx.x * 128 : (W_ - 128);
    const int y0  = blockIdx.y * 4;
    const int b   = blockIdx.z;
    const int tid = threadIdx.x;
    const int wid = tid >> 5;
    const int lane = tid & 31;
    const int gid = lane >> 2;
    const int tig = lane & 3;

    const int warpM  = wid & 7;          // 8 M-warps (64 px each)
    const int warpN  = wid >> 3;         // 2 N-warps x 32 co
    const int rowsel = warpM >> 1;       // output row 0..3
    const int xwbase = (warpM & 1) * 64;

    // ---- Stage feat rows y0-1 .. y0+4 as bf16 pairs, [r][xi][ci] ----
    for (int j = tid; j < 6 * 32 * 130; j += 512) {
        int r   = j / (32 * 130);
        int rem = j - r * (32 * 130);
        int ci2 = rem / 130;
        int xi  = rem - ci2 * 130;
        int yy  = y0 + r - 1;
        int gx  = x0 + xi - 1;
        float f0 = 0.f, f1 = 0.f;
        if ((unsigned)yy < (unsigned)H_ && (unsigned)gx < (unsigned)W_) {
            size_t o = ((size_t)(b * C_ + 2 * ci2) * H_ + yy) * W_ + gx;
            f0 = feat[o];
            f1 = feat[o + (size_t)HW_];
        }
        __nv_bfloat162 v2 = __floats2bfloat162_rn(f0, f1);
        *reinterpret_cast<uint32_t*>(sm + (r * 130 + xi) * SPADB + ci2 * 4) =
            *reinterpret_cast<uint32_t*>(&v2);
    }
    // ---- Stage ALL 9 taps of w1 as bf16 [tap][co][ci] ----
    for (int j = tid; j < 9 * 64 * 32; j += 512) {
        int tap = j >> 11;
        int co  = (j >> 5) & 63;
        int ci2 = j & 31;
        const float* wp = w1 + co * 576 + ci2 * 18 + tap;
        __nv_bfloat162 v2 = __floats2bfloat162_rn(wp[0], wp[9]);
        *reinterpret_cast<uint32_t*>(sm + OFF_W + tap * WTAP + co * SPADB + ci2 * 4) =
            *reinterpret_cast<uint32_t*>(&v2);
    }
    __syncthreads();

    // per-lane ldmatrix offsets
    const uint32_t a_loff = (uint32_t)(((lane & 7) + ((lane >> 3) & 1) * 8) * SPADB
                                       + ((lane >> 4) & 1) * 16);
    const uint32_t b_loff = (uint32_t)((lane & 7) * SPADB + ((lane >> 3) & 1) * 16
                                       + ((lane >> 4) & 1) * (8 * SPADB));
    const uint32_t fbase = sbase + a_loff
        + (uint32_t)((rowsel * 130 + xwbase) * SPADB);
    const uint32_t wbase = sbase + OFF_W + b_loff
        + (uint32_t)(warpN * 32 * SPADB);

    float acc[4][4][4];
    #pragma unroll
    for (int mf = 0; mf < 4; mf++)
        #pragma unroll
        for (int nf = 0; nf < 4; nf++)
            #pragma unroll
            for (int r = 0; r < 4; r++) acc[mf][nf][r] = 0.f;

    uint32_t abuf[2][4][4], bbuf[2][8];

    auto load_iter = [&](int i, uint32_t (*a)[4], uint32_t* bf) {
        const int t  = i >> 2, kc = i & 3;
        const int ky = t / 3,  kx = t - ky * 3;
        const uint32_t frow = fbase
            + (uint32_t)((ky * 130 + kx) * SPADB + kc * 32);
        #pragma unroll
        for (int mf = 0; mf < 4; mf++)
            ldmx4(a[mf], frow + (uint32_t)(mf * 16 * SPADB));
        const uint32_t wrow = wbase + (uint32_t)(t * WTAP + kc * 32);
        ldmx4(bf, wrow);
        ldmx4(bf + 4, wrow + (uint32_t)(16 * SPADB));
    };

    load_iter(0, abuf[0], bbuf[0]);
    #pragma unroll
    for (int i = 0; i < 36; i++) {
        if (i < 35) load_iter(i + 1, abuf[(i + 1) & 1], bbuf[(i + 1) & 1]);
        uint32_t (*a)[4] = abuf[i & 1];
        uint32_t* bf = bbuf[i & 1];
        #pragma unroll
        for (int nf = 0; nf < 4; nf++)
            #pragma unroll
            for (int mf = 0; mf < 4; mf++)
                mma_bf16(acc[mf][nf], a[mf], bf[nf * 2], bf[nf * 2 + 1]);
    }

    // ---- Epilogue: ReLU + store h channel-last bf16 as bf16x2 words ----
    const int yy = y0 + rowsel;
    #pragma unroll
    for (int nf = 0; nf < 4; nf++) {
        const int co = warpN * 32 + nf * 8 + tig * 2;
        #pragma unroll
        for (int mf = 0; mf < 4; mf++) {
            const int xg = x0 + xwbase + mf * 16 + gid;
            size_t base = (((size_t)b * H_ + yy) * W_ + xg) * C_ + co;
            if (xg < W_) {
                __nv_bfloat162 v = __floats2bfloat162_rn(
                    fmaxf(acc[mf][nf][0], 0.f), fmaxf(acc[mf][nf][1], 0.f));
                *reinterpret_cast<uint32_t*>(&g_h[base]) =
                    *reinterpret_cast<uint32_t*>(&v);
            }
            if (xg + 8 < W_) {
                __nv_bfloat162 v = __floats2bfloat162_rn(
                    fmaxf(acc[mf][nf][2], 0.f), fmaxf(acc[mf][nf][3], 0.f));
                *reinterpret_cast<uint32_t*>(&g_h[base + 8 * C_]) =
                    *reinterpret_cast<uint32_t*>(&v);
            }
        }
    }
}

// ---------------------------------------------------------------------------
// Kernel B: 1x1 conv (64->144) via bf16 mma + softmax(9 taps) + depth blend
// + pixel shuffle. CTA = 64 px of one row, 256 threads (8 warps).
// Logits alias the h/w2 staging region; launch_bounds(256,4) caps regs at 64
// -> 4 CTAs/SM (occ 50%).
// ---------------------------------------------------------------------------
#define SHB_OFF   0            // h tile  [64 px][72 bf16]  9216 B   (aliased)
#define SWB_OFF   9216         // w2      [144 co][72 bf16] 20736 B  (aliased)
#define SLOG_OFF  0            // logits  [64][146] f32     37376 B  (aliases above)
#define SDEP_OFF  37376        // depth   [3][66] f32         792 B
#define SMEM_B_BYTES 38168

__global__ __launch_bounds__(256, 4) void mask_upsample_kernel(
    const float* __restrict__ depth, const float* __restrict__ w2,
    float* __restrict__ out)
{
    extern __shared__ char smB[];
    char*  shb  = smB + SHB_OFF;
    char*  swb  = smB + SWB_OFF;
    float* slog = reinterpret_cast<float*>(smB + SLOG_OFF);
    float (*sdep)[66] = reinterpret_cast<float(*)[66]>(smB + SDEP_OFF);

    const int x0  = (blockIdx.x < 6) ? blockIdx.x * 64 : (W_ - 64);
    const int y   = blockIdx.y;
    const int b   = blockIdx.z;
    const int tid = threadIdx.x;
    const int wid = tid >> 5;
    const int lane = tid & 31;
    const int gid = lane >> 2;
    const int tig = lane & 3;
    const int warpM = wid & 3;
    const int warpN = wid >> 2;

    for (int j = tid; j < 64 * 8; j += 256) {
        int px = j >> 3, seg = j & 7;
        int gx = x0 + px;
        uint4 v = make_uint4(0u, 0u, 0u, 0u);
        if (gx < W_)
            v = *reinterpret_cast<const uint4*>(
                g_h + ((((size_t)b * H_ + y) * W_ + gx) * C_ + seg * 8));
        *reinterpret_cast<uint4*>(shb + px * SPADB + seg * 16) = v;
    }
    for (int j = tid; j < 144 * 32; j += 256) {
        int co = j >> 5, ci2 = j & 31;
        const float* wp = w2 + co * 64 + ci2 * 2;
        __nv_bfloat162 v2 = __floats2bfloat162_rn(wp[0], wp[1]);
        *reinterpret_cast<uint32_t*>(swb + co * SPADB + ci2 * 4) =
            *reinterpret_cast<uint32_t*>(&v2);
    }
    for (int i = tid; i < 3 * 66; i += 256) {
        int ry = i / 66, rx = i - ry * 66;
        int gy = y + ry - 1, gx = x0 + rx - 1;
        sdep[ry][rx] = (gy >= 0 && gy < H_ && gx >= 0 && gx < W_)
                       ? depth[((size_t)b * H_ + gy) * W_ + gx] : 0.f;
    }
    __syncthreads();

    // ---- Phase 1: GEMM M=64 N=144 K=64 -> logits in registers ----
    float acc[9][4];
    #pragma unroll
    for (int nf = 0; nf < 9; nf++)
        #pragma unroll
        for (int r = 0; r < 4; r++) acc[nf][r] = 0.f;

    #pragma unroll
    for (int kc = 0; kc < 4; kc++) {
        uint32_t a[4];
        const char* ap = shb + (warpM * 16 + gid) * SPADB + kc * 32 + tig * 4;
        a[0] = *reinterpret_cast<const uint32_t*>(ap);
        a[1] = *reinterpret_cast<const uint32_t*>(ap + 8 * SPADB);
        a[2] = *reinterpret_cast<const uint32_t*>(ap + 16);
        a[3] = *reinterpret_cast<const uint32_t*>(ap + 8 * SPADB + 16);
        #pragma unroll
        for (int nf = 0; nf < 9; nf++) {
            const int co = warpN * 72 + nf * 8 + gid;
            const char* bp = swb + co * SPADB + kc * 32 + tig * 4;
            uint32_t b0 = *reinterpret_cast<const uint32_t*>(bp);
            uint32_t b1 = *reinterpret_cast<const uint32_t*>(bp + 16);
            mma_bf16(acc[nf], a, b0, b1);
        }
    }

    // staging region is dead now; barrier, then reuse it for logits
    __syncthreads();
    {
        const int px = warpM * 16 + gid;
        #pragma unroll
        for (int nf = 0; nf < 9; nf++) {
            const int co = warpN * 72 + nf * 8 + tig * 2;
            *reinterpret_cast<float2*>(&slog[px * 146 + co]) =
                make_float2(acc[nf][0], acc[nf][1]);
            *reinterpret_cast<float2*>(&slog[(px + 8) * 146 + co]) =
                make_float2(acc[nf][2], acc[nf][3]);
        }
    }
    __syncthreads();

    // ---- Phase 2: softmax over taps + depth blend + pixel shuffle ----
    const int px   = tid & 63;
    const int cgrp = tid >> 6;
    float d[9];
    #pragma unroll
    for (int t = 0; t < 9; t++) d[t] = sdep[t / 3][px + (t % 3)];

    float vals[4];
    #pragma unroll
    for (int j = 0; j < 4; j++) {
        const int cell = cgrp * 4 + j;
        float lg[9];
        #pragma unroll
        for (int t = 0; t < 9; t++) lg[t] = slog[px * 146 + t * 16 + cell];
        float mx = lg[0];
        #pragma unroll
        for (int t = 1; t < 9; t++) mx = fmaxf(mx, lg[t]);
        float s = 0.f, v = 0.f;
        #pragma unroll
        for (int t = 0; t < 9; t++) {
            float e = __expf(lg[t] - mx);
            s += e;
            v = fmaf(e, d[t], v);
        }
        vals[j] = v / s;
    }

    const int gx = x0 + px;
    if (gx < W_)
        *reinterpret_cast<float4*>(
            &out[((size_t)b * OH_ + (y * 4 + cgrp)) * OW_ + gx * 4]) =
            make_float4(vals[0], vals[1], vals[2], vals[3]);
}

extern "C" void kernel_launch(void* const* d_in, const int* in_sizes, int n_in,
                              void* d_out, int out_size)
{
    const float* depth = (const float*)d_in[0];
    const float* feat  = (const float*)d_in[1];
    const float* w1    = (const float*)d_in[2];
    const float* w2    = (const float*)d_in[3];
    float* out = (float*)d_out;

    cudaFuncSetAttribute(conv3x3_tc_kernel,
                         cudaFuncAttributeMaxDynamicSharedMemorySize, SMEM_A_BYTES);
    cudaFuncSetAttribute(mask_upsample_kernel,
                         cudaFuncAttributeMaxDynamicSharedMemorySize, SMEM_B_BYTES);

    dim3 gA(4, H_ / 4, B_);                   // 4 x-tiles x 32 y-tiles x 8
    conv3x3_tc_kernel<<<gA, 512, SMEM_A_BYTES>>>(feat, w1);

    dim3 gB(7, H_, B_);                       // 7 x-tiles of 64 px (last clamped)
    mask_upsample_kernel<<<gB, 256, SMEM_B_BYTES>>>(depth, w2, out);
}

// round 11
// speedup vs baseline: 1.4537x; 1.2790x over previous
#include <cuda_runtime.h>
#include <cuda_bf16.h>
#include <cstdint>

#define B_   8
#define C_   64
#define H_   128
#define W_   416
#define OH_  (4 * H_)
#define OW_  (4 * W_)
#define HW_  (H_ * W_)

// Scratch h: conv3x3+relu output, CHANNEL-LAST bf16: [b][y][x][ci] (~54.5 MB).
__device__ __nv_bfloat16 g_h[(size_t)B_ * H_ * W_ * C_];
// Pre-built B-fragment table: [(tap*4+kc)*2+warpN][lane][8] uint32 (72 KB).
__device__ uint32_t g_wpack[72 * 32 * 8];

// ---------------------------------------------------------------------------
// helpers (legacy mma.sync / ldmatrix — compile for plain compute_103)
// ---------------------------------------------------------------------------
__device__ __forceinline__ uint32_t smem_u32(const void* p) {
    uint32_t a;
    asm("{ .reg .u64 t; cvta.to.shared.u64 t, %1; cvt.u32.u64 %0, t; }"
        : "=r"(a) : "l"(p));
    return a;
}

__device__ __forceinline__ void mma_bf16(float* d, const uint32_t* a,
                                         uint32_t b0, uint32_t b1) {
    asm volatile(
        "mma.sync.aligned.m16n8k16.row.col.f32.bf16.bf16.f32 "
        "{%0,%1,%2,%3}, {%4,%5,%6,%7}, {%8,%9}, {%0,%1,%2,%3};"
        : "+f"(d[0]), "+f"(d[1]), "+f"(d[2]), "+f"(d[3])
        : "r"(a[0]), "r"(a[1]), "r"(a[2]), "r"(a[3]), "r"(b0), "r"(b1));
}

__device__ __forceinline__ void ldmx4(uint32_t* r, uint32_t addr) {
    asm volatile(
        "ldmatrix.sync.aligned.m8n8.x4.shared.b16 {%0,%1,%2,%3}, [%4];"
        : "=r"(r[0]), "=r"(r[1]), "=r"(r[2]), "=r"(r[3]) : "r"(addr));
}

#define SPADB  144                      // bytes per ci-row (72 bf16 slots)
#define WTAP   9216                     // per-tap weights: 64*144

// ---------------------------------------------------------------------------
// Kernel W: repack w1 into per-lane B-fragment words via real ldmatrix, so
// kernel A can LDG fragments directly (mapping correct by construction).
// One CTA, 256 threads. smem: [9 taps][64 co][72 ci] bf16 = 82944 B.
// ---------------------------------------------------------------------------
#define SMEM_W_BYTES (9 * WTAP)

__global__ __launch_bounds__(256) void repack_w1_kernel(
    const float* __restrict__ w1)
{
    extern __shared__ char smw[];
    const uint32_t sbase = smem_u32(smw);
    const int tid = threadIdx.x;
    const int wid = tid >> 5;
    const int lane = tid & 31;

    for (int j = tid; j < 9 * 64 * 32; j += 256) {
        int tap = j >> 11;
        int co  = (j >> 5) & 63;
        int ci2 = j & 31;
        const float* wp = w1 + co * 576 + ci2 * 18 + tap;
        __nv_bfloat162 v2 = __floats2bfloat162_rn(wp[0], wp[9]);
        *reinterpret_cast<uint32_t*>(smw + tap * WTAP + co * SPADB + ci2 * 4) =
            *reinterpret_cast<uint32_t*>(&v2);
    }
    __syncthreads();

    const uint32_t b_loff = (uint32_t)((lane & 7) * SPADB + ((lane >> 3) & 1) * 16
                                       + ((lane >> 4) & 1) * (8 * SPADB));
    // 72 units: (tap 0..8) x (kc 0..3) x (warpN 0..1); warp w handles t = w-strided
    for (int u = wid; u < 72; u += 8) {
        const int t  = u >> 3;
        const int r  = u & 7;
        const int kc = r >> 1;
        const int wn = r & 1;
        const uint32_t wrow = sbase + (uint32_t)(t * WTAP + wn * 32 * SPADB + kc * 32)
                            + b_loff;
        uint32_t bf[8];
        ldmx4(bf, wrow);
        ldmx4(bf + 4, wrow + (uint32_t)(16 * SPADB));
        uint32_t* dst = g_wpack + (size_t)u * 256 + lane * 8;
        *reinterpret_cast<uint4*>(dst) =
            make_uint4(bf[0], bf[1], bf[2], bf[3]);
        *reinterpret_cast<uint4*>(dst + 4) =
            make_uint4(bf[4], bf[5], bf[6], bf[7]);
    }
}

// ---------------------------------------------------------------------------
// Kernel A: conv3x3 (pad=1, no bias) + ReLU as bf16 implicit GEMM.
// CTA = 2 rows x 128 px x 64 co, 256 threads (8 warps: 4M x 2N), 2 CTAs/SM.
// A-frags via ldmatrix (4 per iter); B-frags via 2 coalesced LDG.128 from
// g_wpack, double-buffered + prefetched 1 iter ahead. smem = feat only.
// Regs ~110 < 128 cap -> no spill; cross-CTA overlap hides staging.
// ---------------------------------------------------------------------------
#define SMEM_A_BYTES (4 * 130 * SPADB)      // 74880

__global__ __launch_bounds__(256, 2) void conv3x3_tc_kernel(
    const float* __restrict__ feat)
{
    extern __shared__ char sm[];
    const uint32_t sbase = smem_u32(sm);

    const int x0  = (blockIdx.x < 3) ? blockIdx.x * 128 : (W_ - 128);
    const int y0  = blockIdx.y * 2;
    const int b   = blockIdx.z;
    const int tid = threadIdx.x;
    const int wid = tid >> 5;
    const int lane = tid & 31;
    const int gid = lane >> 2;
    const int tig = lane & 3;

    const int warpM  = wid & 3;          // 4 M-warps (64 px each)
    const int warpN  = wid >> 2;         // 2 N-warps x 32 co
    const int rowsel = warpM >> 1;       // output row 0..1
    const int xwbase = (warpM & 1) * 64;

    // ---- Stage feat rows y0-1 .. y0+2 as bf16 pairs, [r][xi][ci] ----
    for (int j = tid; j < 4 * 32 * 130; j += 256) {
        int r   = j / (32 * 130);
        int rem = j - r * (32 * 130);
        int ci2 = rem / 130;
        int xi  = rem - ci2 * 130;
        int yy  = y0 + r - 1;
        int gx  = x0 + xi - 1;
        float f0 = 0.f, f1 = 0.f;
        if ((unsigned)yy < (unsigned)H_ && (unsigned)gx < (unsigned)W_) {
            size_t o = ((size_t)(b * C_ + 2 * ci2) * H_ + yy) * W_ + gx;
            f0 = feat[o];
            f1 = feat[o + (size_t)HW_];
        }
        __nv_bfloat162 v2 = __floats2bfloat162_rn(f0, f1);
        *reinterpret_cast<uint32_t*>(sm + (r * 130 + xi) * SPADB + ci2 * 4) =
            *reinterpret_cast<uint32_t*>(&v2);
    }
    __syncthreads();

    const uint32_t a_loff = (uint32_t)(((lane & 7) + ((lane >> 3) & 1) * 8) * SPADB
                                       + ((lane >> 4) & 1) * 16);
    const uint32_t fbase = sbase + a_loff
        + (uint32_t)((rowsel * 130 + xwbase) * SPADB);
    // B-frag gmem base for this warp: unit u = (t*4+kc)*2 + warpN
    const uint4* wp0 = reinterpret_cast<const uint4*>(g_wpack) + lane * 2;

    float acc[4][4][4];
    #pragma unroll
    for (int mf = 0; mf < 4; mf++)
        #pragma unroll
        for (int nf = 0; nf < 4; nf++)
            #pragma unroll
            for (int r = 0; r < 4; r++) acc[mf][nf][r] = 0.f;

    uint32_t bwq[2][8];
    {
        const uint4* p = wp0 + (size_t)warpN * 64;   // unit 0 = (t0,kc0,warpN)
        uint4 q0 = p[0], q1 = p[1];
        bwq[0][0] = q0.x; bwq[0][1] = q0.y; bwq[0][2] = q0.z; bwq[0][3] = q0.w;
        bwq[0][4] = q1.x; bwq[0][5] = q1.y; bwq[0][6] = q1.z; bwq[0][7] = q1.w;
    }

    #pragma unroll
    for (int i = 0; i < 36; i++) {
        // A fragments for this iter (single-buffered ldmatrix)
        const int t  = i >> 2, kc = i & 3;
        const int ky = t / 3,  kx = t - ky * 3;
        const uint32_t frow = fbase
            + (uint32_t)((ky * 130 + kx) * SPADB + kc * 32);
        uint32_t a[4][4];
        #pragma unroll
        for (int mf = 0; mf < 4; mf++)
            ldmx4(a[mf], frow + (uint32_t)(mf * 16 * SPADB));

        // prefetch next iter's B fragments
        if (i < 35) {
            const int u = (i + 1) * 2 + warpN;
            const uint4* p = wp0 + (size_t)u * 64;
            uint4 q0 = p[0], q1 = p[1];
            uint32_t* dst = bwq[(i + 1) & 1];
            dst[0] = q0.x; dst[1] = q0.y; dst[2] = q0.z; dst[3] = q0.w;
            dst[4] = q1.x; dst[5] = q1.y; dst[6] = q1.z; dst[7] = q1.w;
        }

        const uint32_t* bf = bwq[i & 1];
        #pragma unroll
        for (int nf = 0; nf < 4; nf++)
            #pragma unroll
            for (int mf = 0; mf < 4; mf++)
                mma_bf16(acc[mf][nf], a[mf], bf[nf * 2], bf[nf * 2 + 1]);
    }

    // ---- Epilogue: ReLU + store h channel-last bf16 as bf16x2 words ----
    const int yy = y0 + rowsel;
    #pragma unroll
    for (int nf = 0; nf < 4; nf++) {
        const int co = warpN * 32 + nf * 8 + tig * 2;
        #pragma unroll
        for (int mf = 0; mf < 4; mf++) {
            const int xg = x0 + xwbase + mf * 16 + gid;
            size_t base = (((size_t)b * H_ + yy) * W_ + xg) * C_ + co;
            if (xg < W_) {
                __nv_bfloat162 v = __floats2bfloat162_rn(
                    fmaxf(acc[mf][nf][0], 0.f), fmaxf(acc[mf][nf][1], 0.f));
                *reinterpret_cast<uint32_t*>(&g_h[base]) =
                    *reinterpret_cast<uint32_t*>(&v);
            }
            if (xg + 8 < W_) {
                __nv_bfloat162 v = __floats2bfloat162_rn(
                    fmaxf(acc[mf][nf][2], 0.f), fmaxf(acc[mf][nf][3], 0.f));
                *reinterpret_cast<uint32_t*>(&g_h[base + 8 * C_]) =
                    *reinterpret_cast<uint32_t*>(&v);
            }
        }
    }
}

// ---------------------------------------------------------------------------
// Kernel B: 1x1 conv (64->144) via bf16 mma + softmax(9 taps) + depth blend
// + pixel shuffle. CTA = 64 px of one row, 256 threads (8 warps).
// Logits alias the h/w2 staging region; launch_bounds(256,4) -> 4 CTAs/SM.
// ---------------------------------------------------------------------------
#define SHB_OFF   0            // h tile  [64 px][72 bf16]  9216 B   (aliased)
#define SWB_OFF   9216         // w2      [144 co][72 bf16] 20736 B  (aliased)
#define SLOG_OFF  0            // logits  [64][146] f32     37376 B  (aliases above)
#define SDEP_OFF  37376        // depth   [3][66] f32         792 B
#define SMEM_B_BYTES 38168

__global__ __launch_bounds__(256, 4) void mask_upsample_kernel(
    const float* __restrict__ depth, const float* __restrict__ w2,
    float* __restrict__ out)
{
    extern __shared__ char smB[];
    char*  shb  = smB + SHB_OFF;
    char*  swb  = smB + SWB_OFF;
    float* slog = reinterpret_cast<float*>(smB + SLOG_OFF);
    float (*sdep)[66] = reinterpret_cast<float(*)[66]>(smB + SDEP_OFF);

    const int x0  = (blockIdx.x < 6) ? blockIdx.x * 64 : (W_ - 64);
    const int y   = blockIdx.y;
    const int b   = blockIdx.z;
    const int tid = threadIdx.x;
    const int wid = tid >> 5;
    const int lane = tid & 31;
    const int gid = lane >> 2;
    const int tig = lane & 3;
    const int warpM = wid & 3;
    const int warpN = wid >> 2;

    for (int j = tid; j < 64 * 8; j += 256) {
        int px = j >> 3, seg = j & 7;
        int gx = x0 + px;
        uint4 v = make_uint4(0u, 0u, 0u, 0u);
        if (gx < W_)
            v = *reinterpret_cast<const uint4*>(
                g_h + ((((size_t)b * H_ + y) * W_ + gx) * C_ + seg * 8));
        *reinterpret_cast<uint4*>(shb + px * SPADB + seg * 16) = v;
    }
    for (int j = tid; j < 144 * 32; j += 256) {
        int co = j >> 5, ci2 = j & 31;
        const float* wp = w2 + co * 64 + ci2 * 2;
        __nv_bfloat162 v2 = __floats2bfloat162_rn(wp[0], wp[1]);
        *reinterpret_cast<uint32_t*>(swb + co * SPADB + ci2 * 4) =
            *reinterpret_cast<uint32_t*>(&v2);
    }
    for (int i = tid; i < 3 * 66; i += 256) {
        int ry = i / 66, rx = i - ry * 66;
        int gy = y + ry - 1, gx = x0 + rx - 1;
        sdep[ry][rx] = (gy >= 0 && gy < H_ && gx >= 0 && gx < W_)
                       ? depth[((size_t)b * H_ + gy) * W_ + gx] : 0.f;
    }
    __syncthreads();

    float acc[9][4];
    #pragma unroll
    for (int nf = 0; nf < 9; nf++)
        #pragma unroll
        for (int r = 0; r < 4; r++) acc[nf][r] = 0.f;

    #pragma unroll
    for (int kc = 0; kc < 4; kc++) {
        uint32_t a[4];
        const char* ap = shb + (warpM * 16 + gid) * SPADB + kc * 32 + tig * 4;
        a[0] = *reinterpret_cast<const uint32_t*>(ap);
        a[1] = *reinterpret_cast<const uint32_t*>(ap + 8 * SPADB);
        a[2] = *reinterpret_cast<const uint32_t*>(ap + 16);
        a[3] = *reinterpret_cast<const uint32_t*>(ap + 8 * SPADB + 16);
        #pragma unroll
        for (int nf = 0; nf < 9; nf++) {
            const int co = warpN * 72 + nf * 8 + gid;
            const char* bp = swb + co * SPADB + kc * 32 + tig * 4;
            uint32_t b0 = *reinterpret_cast<const uint32_t*>(bp);
            uint32_t b1 = *reinterpret_cast<const uint32_t*>(bp + 16);
            mma_bf16(acc[nf], a, b0, b1);
        }
    }

    __syncthreads();
    {
        const int px = warpM * 16 + gid;
        #pragma unroll
        for (int nf = 0; nf < 9; nf++) {
            const int co = warpN * 72 + nf * 8 + tig * 2;
            *reinterpret_cast<float2*>(&slog[px * 146 + co]) =
                make_float2(acc[nf][0], acc[nf][1]);
            *reinterpret_cast<float2*>(&slog[(px + 8) * 146 + co]) =
                make_float2(acc[nf][2], acc[nf][3]);
        }
    }
    __syncthreads();

    const int px   = tid & 63;
    const int cgrp = tid >> 6;
    float d[9];
    #pragma unroll
    for (int t = 0; t < 9; t++) d[t] = sdep[t / 3][px + (t % 3)];

    float vals[4];
    #pragma unroll
    for (int j = 0; j < 4; j++) {
        const int cell = cgrp * 4 + j;
        float lg[9];
        #pragma unroll
        for (int t = 0; t < 9; t++) lg[t] = slog[px * 146 + t * 16 + cell];
        float mx = lg[0];
        #pragma unroll
        for (int t = 1; t < 9; t++) mx = fmaxf(mx, lg[t]);
        float s = 0.f, v = 0.f;
        #pragma unroll
        for (int t = 0; t < 9; t++) {
            float e = __expf(lg[t] - mx);
            s += e;
            v = fmaf(e, d[t], v);
        }
        vals[j] = v / s;
    }

    const int gx = x0 + px;
    if (gx < W_)
        *reinterpret_cast<float4*>(
            &out[((size_t)b * OH_ + (y * 4 + cgrp)) * OW_ + gx * 4]) =
            make_float4(vals[0], vals[1], vals[2], vals[3]);
}

extern "C" void kernel_launch(void* const* d_in, const int* in_sizes, int n_in,
                              void* d_out, int out_size)
{
    const float* depth = (const float*)d_in[0];
    const float* feat  = (const float*)d_in[1];
    const float* w1    = (const float*)d_in[2];
    const float* w2    = (const float*)d_in[3];
    float* out = (float*)d_out;

    cudaFuncSetAttribute(repack_w1_kernel,
                         cudaFuncAttributeMaxDynamicSharedMemorySize, SMEM_W_BYTES);
    cudaFuncSetAttribute(conv3x3_tc_kernel,
                         cudaFuncAttributeMaxDynamicSharedMemorySize, SMEM_A_BYTES);
    cudaFuncSetAttribute(mask_upsample_kernel,
                         cudaFuncAttributeMaxDynamicSharedMemorySize, SMEM_B_BYTES);

    repack_w1_kernel<<<1, 256, SMEM_W_BYTES>>>(w1);

    dim3 gA(4, H_ / 2, B_);                   // 4 x-tiles x 64 y-pairs x 8
    conv3x3_tc_kernel<<<gA, 256, SMEM_A_BYTES>>>(feat);

    dim3 gB(7, H_, B_);                       // 7 x-tiles of 64 px (last clamped)
    mask_upsample_kernel<<<gB, 256, SMEM_B_BYTES>>>(depth, w2, out);
}